// round 10
// baseline (speedup 1.0000x reference)
#include <cuda_runtime.h>
#include <cuda_fp16.h>
#include <stdint.h>
#include <math.h>

// Problem constants
#define BB 64
#define LL 512
#define DD 768
#define HH 768

static const int    M_ROWS = BB * LL;                  // 32768
static const size_t PLH = (size_t)BB * LL * HH;        // 25165824
static const size_t ALL = (size_t)BB * LL * LL;        // 16777216

__device__ __align__(16) float g_scratch[6 * 25165824ULL + 3 * 16777216ULL + 4 * 32768ULL + 2359296ULL];

// ---------------------------------------------------------------------------
// helpers
// ---------------------------------------------------------------------------
__device__ __forceinline__ void cp16(void* s, const void* g) {
    uint32_t sa = (uint32_t)__cvta_generic_to_shared(s);
    asm volatile("cp.async.cg.shared.global [%0], [%1], 16;" :: "r"(sa), "l"(g));
}
__device__ __forceinline__ void cp_commit() { asm volatile("cp.async.commit_group;"); }
__device__ __forceinline__ void cp_wait1()  { asm volatile("cp.async.wait_group 1;"); }

__device__ __forceinline__ void ldsm_x4(uint32_t* r, uint32_t addr) {
    asm volatile("ldmatrix.sync.aligned.m8n8.x4.shared.b16 {%0,%1,%2,%3}, [%4];"
        : "=r"(r[0]), "=r"(r[1]), "=r"(r[2]), "=r"(r[3]) : "r"(addr));
}
__device__ __forceinline__ void ldsm_x4t(uint32_t* r, uint32_t addr) {
    asm volatile("ldmatrix.sync.aligned.m8n8.x4.trans.shared.b16 {%0,%1,%2,%3}, [%4];"
        : "=r"(r[0]), "=r"(r[1]), "=r"(r[2]), "=r"(r[3]) : "r"(addr));
}
__device__ __forceinline__ void mma16(float* c, const uint32_t* a, const uint32_t* b) {
    asm volatile(
        "mma.sync.aligned.m16n8k16.row.col.f32.f16.f16.f32 "
        "{%0,%1,%2,%3},{%4,%5,%6,%7},{%8,%9},{%0,%1,%2,%3};"
        : "+f"(c[0]), "+f"(c[1]), "+f"(c[2]), "+f"(c[3])
        : "r"(a[0]), "r"(a[1]), "r"(a[2]), "r"(a[3]), "r"(b[0]), "r"(b[1]));
}

// monotone float<->uint encoding for atomicMax on floats of any sign
__device__ __forceinline__ uint32_t encf(float f) {
    uint32_t u = __float_as_uint(f);
    return u ^ (uint32_t)(((int32_t)u >> 31) | 0x80000000);
}
__device__ __forceinline__ float decf(uint32_t u) {
    u = (u & 0x80000000u) ? (u ^ 0x80000000u) : ~u;
    return __uint_as_float(u);
}

// SMEM staging (BK = 64, 3 stages):
//  A tile: [128][72] halves, pitch 144 B, stage = 18432 B  (conflict-free ldmatrix)
//  B KN:   [64][136] halves, pitch 272 B, stage = 17408 B
//  B NT:   same layout as A
#define A_STG_B 18432u
#define B_STG_B 17408u
#define A_STG_H 9216
#define B_STG_H 8704

#define COMPUTE64_KN(buf)                                                      \
    _Pragma("unroll")                                                          \
    for (int ks = 0; ks < 4; ks++) {                                           \
        uint32_t af[4][4], bt0[4], bt1[4];                                     \
        _Pragma("unroll")                                                      \
        for (int fm = 0; fm < 4; fm++)                                         \
            ldsm_x4(af[fm], a_addr + (buf) * A_STG_B + ks * 32u + fm * 2304u); \
        ldsm_x4t(bt0, b_addr + (buf) * B_STG_B + ks * 4352u);                  \
        ldsm_x4t(bt1, b_addr + (buf) * B_STG_B + ks * 4352u + 32u);            \
        uint32_t bf[4][2] = {{bt0[0], bt0[1]}, {bt0[2], bt0[3]},               \
                             {bt1[0], bt1[1]}, {bt1[2], bt1[3]}};              \
        _Pragma("unroll")                                                      \
        for (int fm = 0; fm < 4; fm++)                                         \
            _Pragma("unroll")                                                  \
            for (int fn = 0; fn < 4; fn++)                                     \
                mma16(acc[fm][fn], af[fm], bf[fn]);                            \
    }

#define COMPUTE64_NT(buf)                                                      \
    _Pragma("unroll")                                                          \
    for (int ks = 0; ks < 4; ks++) {                                           \
        uint32_t af[4][4], bt0[4], bt1[4];                                     \
        _Pragma("unroll")                                                      \
        for (int fm = 0; fm < 4; fm++)                                         \
            ldsm_x4(af[fm], a_addr + (buf) * A_STG_B + ks * 32u + fm * 2304u); \
        ldsm_x4(bt0, bn_addr + (buf) * A_STG_B + ks * 32u);                    \
        ldsm_x4(bt1, bn_addr + (buf) * A_STG_B + ks * 32u + 2304u);            \
        uint32_t bf[4][2] = {{bt0[0], bt0[2]}, {bt0[1], bt0[3]},               \
                             {bt1[0], bt1[2]}, {bt1[1], bt1[3]}};              \
        _Pragma("unroll")                                                      \
        for (int fm = 0; fm < 4; fm++)                                         \
            _Pragma("unroll")                                                  \
            for (int fn = 0; fn < 4; fn++)                                     \
                mma16(acc[fm][fn], af[fm], bf[fn]);                            \
    }

#define LANE_SETUP                                                             \
    const int t = threadIdx.x;                                                 \
    const int w = t >> 5, l = t & 31, g = l >> 2, q = l & 3;                   \
    const int wm = w >> 2, wn = w & 3;

#define A_ADDR_EXPR (uint32_t)(((wm * 64 + (l & 7) + ((l & 8) ? 8 : 0)) * 72 + ((l & 16) ? 8 : 0)) << 1)
#define B_ADDR_EXPR (uint32_t)((((l & 7) + ((l & 8) ? 8 : 0)) * 136 + wn * 32 + ((l & 16) ? 8 : 0)) << 1)
#define BN_ADDR_EXPR (uint32_t)(((wn * 32 + (l & 7) + ((l & 8) ? 8 : 0)) * 72 + ((l & 16) ? 8 : 0)) << 1)

static const int KN_SMEM = 3 * (A_STG_B + B_STG_B);   // 107520
static const int NT_SMEM = 3 * 2 * A_STG_B;           // 110592

// 3-stage pipeline over BK=64 stages
#define PIPE3_PROLOG()                                                         \
    LOADT(0, 0);  cp_commit();                                                 \
    LOADT(1, 64); cp_commit();

#define PIPE3_BODY(COMPUTE)                                                    \
    {                                                                          \
        int buf = 0, ldst = 2;                                                 \
        for (int kt = 0; kt < nt; kt++) {                                      \
            cp_wait1();                                                        \
            __syncthreads();                                                   \
            if (kt + 2 < nt) { LOADT(ldst, (kt + 2) * 64); }                   \
            cp_commit();                                                       \
            COMPUTE(buf);                                                      \
            if (++buf == 3) buf = 0;                                           \
            if (++ldst == 3) ldst = 0;                                         \
        }                                                                      \
    }

// ---------------------------------------------------------------------------
// converts
// ---------------------------------------------------------------------------
__global__ void k_cvth2(const float* __restrict__ s0, const float* __restrict__ s1,
                        __half* __restrict__ d0, __half* __restrict__ d1, int n)
{
    const float* src = blockIdx.z ? s1 : s0;
    __half* dst = blockIdx.z ? d1 : d0;
    int i = (blockIdx.x * blockDim.x + threadIdx.x) * 4;
    if (i < n) {
        float4 v = *(const float4*)(src + i);
        *(half2*)(dst + i)     = __floats2half2_rn(v.x, v.y);
        *(half2*)(dst + i + 2) = __floats2half2_rn(v.z, v.w);
    }
}
__global__ void k_cvtw(const float* __restrict__ w0, const float* __restrict__ w1,
                       const float* __restrict__ w2,
                       __half* __restrict__ d0, __half* __restrict__ d1, __half* __restrict__ d2)
{
    int z = blockIdx.z;
    const float* src = (z == 0) ? w0 : (z == 1 ? w1 : w2);
    __half* dst = (z == 0) ? d0 : (z == 1 ? d1 : d2);
    int n = (z == 2) ? 2 * HH * HH : DD * HH;
    int i = (blockIdx.x * blockDim.x + threadIdx.x) * 4;
    if (i < n) {
        float4 v = *(const float4*)(src + i);
        *(half2*)(dst + i)     = __floats2half2_rn(v.x, v.y);
        *(half2*)(dst + i + 2) = __floats2half2_rn(v.z, v.w);
    }
}

// ---------------------------------------------------------------------------
// paired proj / attend-F: C = half(relu(A @ W + bias) * mask)   (z selects a/b)
// ---------------------------------------------------------------------------
__global__ __launch_bounds__(256, 2) void k_proj(
    const __half* __restrict__ Aa, const __half* __restrict__ Ab,
    const __half* __restrict__ W, const float* __restrict__ bias,
    const int* __restrict__ ma, const int* __restrict__ mb,
    __half* __restrict__ Ca, __half* __restrict__ Cb, int K)
{
    extern __shared__ __half sm[];
    __half* smA = sm;
    __half* smB = sm + 3 * A_STG_H;
    LANE_SETUP
    const __half* A = blockIdx.z ? Ab : Aa;
    const int* mask = blockIdx.z ? mb : ma;
    __half* C = blockIdx.z ? Cb : Ca;
    const int m0 = blockIdx.y * 128, n0 = blockIdx.x * 128;
    const uint32_t a_base = (uint32_t)__cvta_generic_to_shared(smA);
    const uint32_t b_base = (uint32_t)__cvta_generic_to_shared(smB);
    const uint32_t a_addr = a_base + A_ADDR_EXPR;
    const uint32_t b_addr = b_base + B_ADDR_EXPR;
    float acc[4][4][4] = {};
    const int nt = K / 64;
#define LOADT(st, k0)                                                                       \
    do {                                                                                    \
        _Pragma("unroll")                                                                   \
        for (int p = 0; p < 4; p++) {                                                       \
            int id = t + p * 256;                                                           \
            int arow = id >> 3, ac = id & 7;                                                \
            cp16(smA + (st) * A_STG_H + arow * 72 + ac * 8,                                 \
                 A + (size_t)(m0 + arow) * K + (k0) + ac * 8);                              \
            int brow = id >> 4, bc = id & 15;                                               \
            cp16(smB + (st) * B_STG_H + brow * 136 + bc * 8,                                \
                 W + (size_t)((k0) + brow) * HH + n0 + bc * 8);                             \
        }                                                                                   \
    } while (0)
    PIPE3_PROLOG()
    PIPE3_BODY(COMPUTE64_KN)
#undef LOADT
    const int mbase = m0 + wm * 64, nbase = n0 + wn * 32;
#pragma unroll
    for (int fm = 0; fm < 4; fm++) {
        int m = mbase + fm * 16 + g;
        float mk0 = mask ? (float)mask[m] : 1.0f;
        float mk1 = mask ? (float)mask[m + 8] : 1.0f;
#pragma unroll
        for (int fn = 0; fn < 4; fn++) {
            int n = nbase + fn * 8 + 2 * q;
            float b0 = bias[n], b1 = bias[n + 1];
            *(half2*)&C[(size_t)m * HH + n] =
                __floats2half2_rn(fmaxf(acc[fm][fn][0] + b0, 0.f) * mk0,
                                  fmaxf(acc[fm][fn][1] + b1, 0.f) * mk0);
            *(half2*)&C[(size_t)(m + 8) * HH + n] =
                __floats2half2_rn(fmaxf(acc[fm][fn][2] + b0, 0.f) * mk1,
                                  fmaxf(acc[fm][fn][3] + b1, 0.f) * mk1);
        }
    }
}

// ---------------------------------------------------------------------------
// att[b,i,j] = Fa[b,i,:] . Fb[b,j,:]  (NT), fp32 out + fused row/col max atomics
// ---------------------------------------------------------------------------
__global__ __launch_bounds__(256, 2) void k_att(
    const __half* __restrict__ Fa, const __half* __restrict__ Fb, float* __restrict__ att,
    uint32_t* __restrict__ rm, uint32_t* __restrict__ cm)
{
    extern __shared__ __half sm[];
    __half* smA = sm;
    __half* smB = sm + 3 * A_STG_H;
    LANE_SETUP
    const int b = blockIdx.z;
    const int m0 = blockIdx.y * 128, n0 = blockIdx.x * 128;
    const __half* Ab = Fa + (size_t)b * LL * HH;
    const __half* Bb = Fb + (size_t)b * LL * HH;
    const uint32_t a_base = (uint32_t)__cvta_generic_to_shared(smA);
    const uint32_t b_base = (uint32_t)__cvta_generic_to_shared(smB);
    const uint32_t a_addr  = a_base + A_ADDR_EXPR;
    const uint32_t bn_addr = b_base + BN_ADDR_EXPR;
    float acc[4][4][4] = {};
    const int nt = HH / 64;
#define LOADT(st, k0)                                                                       \
    do {                                                                                    \
        _Pragma("unroll")                                                                   \
        for (int p = 0; p < 4; p++) {                                                       \
            int id = t + p * 256;                                                           \
            int row = id >> 3, cc = id & 7;                                                 \
            cp16(smA + (st) * A_STG_H + row * 72 + cc * 8,                                  \
                 Ab + (size_t)(m0 + row) * HH + (k0) + cc * 8);                             \
            cp16(smB + (st) * A_STG_H + row * 72 + cc * 8,                                  \
                 Bb + (size_t)(n0 + row) * HH + (k0) + cc * 8);                             \
        }                                                                                   \
    } while (0)
    PIPE3_PROLOG()
    PIPE3_BODY(COMPUTE64_NT)
#undef LOADT
    const int mbase = m0 + wm * 64, nbase = n0 + wn * 32;
#pragma unroll
    for (int fm = 0; fm < 4; fm++) {
        int m = mbase + fm * 16 + g;
#pragma unroll
        for (int fn = 0; fn < 4; fn++) {
            int n = nbase + fn * 8 + 2 * q;
            *(float2*)&att[((size_t)b * LL + m) * LL + n] =
                make_float2(acc[fm][fn][0], acc[fm][fn][1]);
            *(float2*)&att[((size_t)b * LL + m + 8) * LL + n] =
                make_float2(acc[fm][fn][2], acc[fm][fn][3]);
        }
    }
    // fused row maxes -> global atomicMax
#pragma unroll
    for (int fm = 0; fm < 4; fm++) {
        float r0 = acc[fm][0][0], r1 = acc[fm][0][2];
#pragma unroll
        for (int fn = 0; fn < 4; fn++) {
            r0 = fmaxf(r0, fmaxf(acc[fm][fn][0], acc[fm][fn][1]));
            r1 = fmaxf(r1, fmaxf(acc[fm][fn][2], acc[fm][fn][3]));
        }
        r0 = fmaxf(r0, __shfl_xor_sync(0xffffffffu, r0, 1));
        r0 = fmaxf(r0, __shfl_xor_sync(0xffffffffu, r0, 2));
        r1 = fmaxf(r1, __shfl_xor_sync(0xffffffffu, r1, 1));
        r1 = fmaxf(r1, __shfl_xor_sync(0xffffffffu, r1, 2));
        if (q == 0) {
            int m = mbase + fm * 16 + g;
            atomicMax(&rm[b * LL + m], encf(r0));
            atomicMax(&rm[b * LL + m + 8], encf(r1));
        }
    }
    // fused col maxes
#pragma unroll
    for (int fn = 0; fn < 4; fn++) {
        float c0 = acc[0][fn][0], c1 = acc[0][fn][1];
#pragma unroll
        for (int fm = 0; fm < 4; fm++) {
            c0 = fmaxf(c0, fmaxf(acc[fm][fn][0], acc[fm][fn][2]));
            c1 = fmaxf(c1, fmaxf(acc[fm][fn][1], acc[fm][fn][3]));
        }
        c0 = fmaxf(c0, __shfl_xor_sync(0xffffffffu, c0, 4));
        c0 = fmaxf(c0, __shfl_xor_sync(0xffffffffu, c0, 8));
        c0 = fmaxf(c0, __shfl_xor_sync(0xffffffffu, c0, 16));
        c1 = fmaxf(c1, __shfl_xor_sync(0xffffffffu, c1, 4));
        c1 = fmaxf(c1, __shfl_xor_sync(0xffffffffu, c1, 8));
        c1 = fmaxf(c1, __shfl_xor_sync(0xffffffffu, c1, 16));
        if (g == 0) {
            int n = nbase + fn * 8 + 2 * q;
            atomicMax(&cm[b * LL + n], encf(c0));
            atomicMax(&cm[b * LL + n + 1], encf(c1));
        }
    }
}

// ---------------------------------------------------------------------------
// map: att -> S1u [b,i,j], S2tu [b,j,i] (unnormalized, half), accumulates rs, cs
// ---------------------------------------------------------------------------
__global__ void k_map(const float* __restrict__ att,
                      const int* __restrict__ a_mask, const int* __restrict__ b_mask,
                      const uint32_t* __restrict__ rm, const uint32_t* __restrict__ cm,
                      float* __restrict__ rs, float* __restrict__ cs,
                      __half* __restrict__ S1, __half* __restrict__ S2t)
{
    const int bb = blockIdx.z;
    const int i0 = blockIdx.y * 32, j0 = blockIdx.x * 32;
    const int tx = threadIdx.x, ty = threadIdx.y;
    const int tid = ty * 32 + tx;
    __shared__ float rmv[32], ermv[32], amv[32];
    __shared__ float ecm[32], bmv[32];
    __shared__ float s2t_sh[32][33];
    __shared__ float colp[8][32];
    if (tid < 32) {
        float c = decf(cm[bb * LL + j0 + tid]);
        ecm[tid] = __expf(-c);
        bmv[tid] = 768.0f * (float)b_mask[bb * LL + j0 + tid];
    } else if (tid < 64) {
        int r = tid - 32;
        float rf = decf(rm[bb * LL + i0 + r]);
        rmv[r] = rf;
        ermv[r] = __expf(rf);
        amv[r] = (float)a_mask[bb * LL + i0 + r];
    }
    __syncthreads();
    float colsum = 0.f;
    for (int r = ty; r < 32; r += 8) {
        const int i = i0 + r;
        float a = att[((size_t)bb * LL + i) * LL + j0 + tx];
        float E = __expf(a - rmv[r]) * (amv[r] * bmv[tx]);
        S1[((size_t)bb * LL + i) * LL + j0 + tx] = __float2half_rn(E);
        float s2 = E * ermv[r] * ecm[tx];
        s2t_sh[tx][r] = s2;
        colsum += s2;
        float rsum = E;
#pragma unroll
        for (int o = 16; o > 0; o >>= 1) rsum += __shfl_xor_sync(0xffffffffu, rsum, o);
        if (tx == 0) atomicAdd(&rs[bb * LL + i], rsum);
    }
    colp[ty][tx] = colsum;
    __syncthreads();
    if (ty == 0) {
        float c = 0.f;
#pragma unroll
        for (int k = 0; k < 8; k++) c += colp[k][tx];
        atomicAdd(&cs[bb * LL + j0 + tx], c);
    }
    for (int r = ty; r < 32; r += 8)
        S2t[((size_t)bb * LL + j0 + r) * LL + i0 + tx] = __float2half_rn(s2t_sh[r][tx]);
}

// ---------------------------------------------------------------------------
// paired ctx (NN, K=512): deferred softmax normalization in epilogue
// ---------------------------------------------------------------------------
__global__ __launch_bounds__(256, 2) void k_ctx(
    const __half* __restrict__ Sa, const __half* __restrict__ Sb,
    const __half* __restrict__ Pa, const __half* __restrict__ Pb,
    const float* __restrict__ sca, const float* __restrict__ scb,
    __half* __restrict__ Ca, __half* __restrict__ Cb)
{
    extern __shared__ __half sm[];
    __half* smA = sm;
    __half* smB = sm + 3 * A_STG_H;
    LANE_SETUP
    const int pair = blockIdx.z >> 6;
    const int b = blockIdx.z & 63;
    const __half* S = pair ? Sb : Sa;
    const __half* P = pair ? Pb : Pa;
    const float* sc = pair ? scb : sca;
    __half* C = pair ? Cb : Ca;
    const int m0 = blockIdx.y * 128, n0 = blockIdx.x * 128;
    const __half* Abp = S + (size_t)b * LL * LL;
    const __half* Bbp = P + (size_t)b * LL * HH;
    const uint32_t a_base = (uint32_t)__cvta_generic_to_shared(smA);
    const uint32_t b_base = (uint32_t)__cvta_generic_to_shared(smB);
    const uint32_t a_addr = a_base + A_ADDR_EXPR;
    const uint32_t b_addr = b_base + B_ADDR_EXPR;
    float acc[4][4][4] = {};
    const int nt = LL / 64;
#define LOADT(st, k0)                                                                       \
    do {                                                                                    \
        _Pragma("unroll")                                                                   \
        for (int p = 0; p < 4; p++) {                                                       \
            int id = t + p * 256;                                                           \
            int arow = id >> 3, ac = id & 7;                                                \
            cp16(smA + (st) * A_STG_H + arow * 72 + ac * 8,                                 \
                 Abp + (size_t)(m0 + arow) * LL + (k0) + ac * 8);                           \
            int brow = id >> 4, bc = id & 15;                                               \
            cp16(smB + (st) * B_STG_H + brow * 136 + bc * 8,                                \
                 Bbp + (size_t)((k0) + brow) * HH + n0 + bc * 8);                           \
        }                                                                                   \
    } while (0)
    PIPE3_PROLOG()
    PIPE3_BODY(COMPUTE64_KN)
#undef LOADT
    const int mbase = m0 + wm * 64, nbase = n0 + wn * 32;
#pragma unroll
    for (int fm = 0; fm < 4; fm++) {
        int m = mbase + fm * 16 + g;
        float s0 = 1.0f / (sc[b * LL + m] + 1e-8f);
        float s1v = 1.0f / (sc[b * LL + m + 8] + 1e-8f);
#pragma unroll
        for (int fn = 0; fn < 4; fn++) {
            int n = nbase + fn * 8 + 2 * q;
            *(half2*)&C[((size_t)b * LL + m) * HH + n] =
                __floats2half2_rn(acc[fm][fn][0] * s0, acc[fm][fn][1] * s0);
            *(half2*)&C[((size_t)b * LL + m + 8) * HH + n] =
                __floats2half2_rn(acc[fm][fn][2] * s1v, acc[fm][fn][3] * s1v);
        }
    }
}

// ---------------------------------------------------------------------------
// paired compare + aggregate
// ---------------------------------------------------------------------------
__global__ __launch_bounds__(256, 2) void k_cmp(
    const __half* __restrict__ Pa, const __half* __restrict__ Pb,
    const __half* __restrict__ Xa, const __half* __restrict__ Xb,
    const __half* __restrict__ Wg, const float* __restrict__ bg,
    const int* __restrict__ ma, const int* __restrict__ mb,
    float* __restrict__ out)
{
    extern __shared__ __half sm[];
    __half* smA = sm;
    __half* smB = sm + 3 * A_STG_H;
    __shared__ float red_s[128][2];
    __shared__ float red_m[128][2];
    LANE_SETUP
    const int z = blockIdx.z;
    const __half* P = z ? Pb : Pa;
    const __half* CTX = z ? Xb : Xa;
    const int* mask = z ? mb : ma;
    const int sumoff = z ? 768 : 0, maxoff = z ? 2304 : 1536;
    const int m0 = blockIdx.y * 128, n0 = blockIdx.x * 128;
    const uint32_t a_base = (uint32_t)__cvta_generic_to_shared(smA);
    const uint32_t b_base = (uint32_t)__cvta_generic_to_shared(smB);
    const uint32_t a_addr = a_base + A_ADDR_EXPR;
    const uint32_t b_addr = b_base + B_ADDR_EXPR;
    float acc[4][4][4] = {};
    const int nt = (2 * HH) / 64;  // 24
#define LOADT(st, k0)                                                                       \
    do {                                                                                    \
        const __half* Asrc = ((k0) < HH) ? P : CTX;                                         \
        const int kk0 = ((k0) < HH) ? (k0) : ((k0) - HH);                                   \
        _Pragma("unroll")                                                                   \
        for (int p = 0; p < 4; p++) {                                                       \
            int id = t + p * 256;                                                           \
            int arow = id >> 3, ac = id & 7;                                                \
            cp16(smA + (st) * A_STG_H + arow * 72 + ac * 8,                                 \
                 Asrc + (size_t)(m0 + arow) * HH + kk0 + ac * 8);                           \
            int brow = id >> 4, bc = id & 15;                                               \
            cp16(smB + (st) * B_STG_H + brow * 136 + bc * 8,                                \
                 Wg + (size_t)((k0) + brow) * HH + n0 + bc * 8);                            \
        }                                                                                   \
    } while (0)
    PIPE3_PROLOG()
    PIPE3_BODY(COMPUTE64_KN)
#undef LOADT
    const int mbase = m0 + wm * 64, nbase = n0 + wn * 32;
    float psum[4][2] = {}, pmax[4][2] = {};
#pragma unroll
    for (int fm = 0; fm < 4; fm++) {
        int m = mbase + fm * 16 + g;
        float mk0 = (float)mask[m];
        float mk1 = (float)mask[m + 8];
#pragma unroll
        for (int fn = 0; fn < 4; fn++) {
            int n = nbase + fn * 8 + 2 * q;
            float b0 = bg[n], b1 = bg[n + 1];
            float v00 = fmaxf(acc[fm][fn][0] + b0, 0.f) * mk0;
            float v01 = fmaxf(acc[fm][fn][1] + b1, 0.f) * mk0;
            float v10 = fmaxf(acc[fm][fn][2] + b0, 0.f) * mk1;
            float v11 = fmaxf(acc[fm][fn][3] + b1, 0.f) * mk1;
            psum[fn][0] += v00 + v10;
            psum[fn][1] += v01 + v11;
            pmax[fn][0] = fmaxf(pmax[fn][0], fmaxf(v00, v10));
            pmax[fn][1] = fmaxf(pmax[fn][1], fmaxf(v01, v11));
        }
    }
#pragma unroll
    for (int fn = 0; fn < 4; fn++)
#pragma unroll
        for (int e = 0; e < 2; e++) {
#pragma unroll
            for (int o = 4; o < 32; o <<= 1) {
                psum[fn][e] += __shfl_xor_sync(0xffffffffu, psum[fn][e], o);
                pmax[fn][e] = fmaxf(pmax[fn][e], __shfl_xor_sync(0xffffffffu, pmax[fn][e], o));
            }
        }
    if (l < 4) {
#pragma unroll
        for (int fn = 0; fn < 4; fn++)
#pragma unroll
            for (int e = 0; e < 2; e++) {
                int c = wn * 32 + fn * 8 + 2 * q + e;
                red_s[c][wm] = psum[fn][e];
                red_m[c][wm] = pmax[fn][e];
            }
    }
    __syncthreads();
    if (t < 128) {
        const int bb = m0 >> 9;
        float s = red_s[t][0] + red_s[t][1];
        float mx = fmaxf(red_m[t][0], red_m[t][1]);
        atomicAdd(&out[bb * 3072 + sumoff + n0 + t], s);
        atomicMax((int*)&out[bb * 3072 + maxoff + n0 + t], __float_as_int(mx));
    }
}

// zero out + stats accumulators (rm/cm encoded maxes, rs/cs sums)
__global__ void k_zero(float* __restrict__ out, float* __restrict__ stats)
{
    int i = blockIdx.x * blockDim.x + threadIdx.x;
    if (i < BB * 4 * HH) out[i] = 0.0f;
    if (i < 4 * M_ROWS) stats[i] = 0.0f;
}

extern "C" void kernel_launch(void* const* d_in, const int* in_sizes, int n_in,
                              void* d_out, int out_size)
{
    const float* a_embeds = (const float*)d_in[0];
    const float* b_embeds = (const float*)d_in[1];
    const int*   a_mask   = (const int*)d_in[2];
    const int*   b_mask   = (const int*)d_in[3];
    const float* Wp = (const float*)d_in[4];
    const float* bp = (const float*)d_in[5];
    const float* Wf = (const float*)d_in[6];
    const float* bf = (const float*)d_in[7];
    const float* Wg = (const float*)d_in[8];
    const float* bg = (const float*)d_in[9];
    float* out = (float*)d_out;

    float* base = nullptr;
    cudaGetSymbolAddress((void**)&base, g_scratch);
    float* att = base;
    float* rm  = att + ALL;          // encoded uint maxes
    float* cm  = rm + M_ROWS;
    float* rs  = cm + M_ROWS;
    float* cs  = rs + M_ROWS;
    __half* ah    = (__half*)(cs + M_ROWS);
    __half* bh    = ah + PLH;
    __half* ap    = bh + PLH;
    __half* bp_   = ap + PLH;
    __half* Fa    = bp_ + PLH;
    __half* Fb    = Fa + PLH;
    __half* beta  = Fb + PLH;
    __half* alpha = beta + PLH;
    __half* S1    = alpha + PLH;
    __half* S2t   = S1 + ALL;
    __half* hWp   = S2t + ALL;
    __half* hWf   = hWp + DD * HH;
    __half* hWg   = hWf + HH * HH;

    cudaFuncSetAttribute(k_proj, cudaFuncAttributeMaxDynamicSharedMemorySize, KN_SMEM);
    cudaFuncSetAttribute(k_att,  cudaFuncAttributeMaxDynamicSharedMemorySize, NT_SMEM);
    cudaFuncSetAttribute(k_ctx,  cudaFuncAttributeMaxDynamicSharedMemorySize, KN_SMEM);
    cudaFuncSetAttribute(k_cmp,  cudaFuncAttributeMaxDynamicSharedMemorySize, KN_SMEM);

    k_zero<<<(BB * 4 * HH + 1023) / 1024, 1024>>>(out, rm);

    // fp32 -> fp16 conversions
    k_cvth2<<<dim3((int)((PLH / 4 + 255) / 256), 1, 2), 256>>>(a_embeds, b_embeds, ah, bh, (int)PLH);
    k_cvtw<<<dim3((2 * HH * HH / 4 + 255) / 256, 1, 3), 256>>>(Wp, Wf, Wg, hWp, hWf, hWg);

    // shared projection FFN (paired a/b)
    k_proj<<<dim3(6, 256, 2), 256, KN_SMEM>>>(ah, bh, hWp, bp, nullptr, nullptr, ap, bp_, DD);

    // attend features (paired, relu + mask)
    k_proj<<<dim3(6, 256, 2), 256, KN_SMEM>>>(ap, bp_, hWf, bf, a_mask, b_mask, Fa, Fb, HH);

    // attention scores + fused row/col max
    k_att<<<dim3(4, 4, 64), 256, NT_SMEM>>>(Fa, Fb, att, (uint32_t*)rm, (uint32_t*)cm);

    // map: unnormalized softmax numerators + sum accumulation
    k_map<<<dim3(16, 16, 64), dim3(32, 8)>>>(att, a_mask, b_mask,
                                             (const uint32_t*)rm, (const uint32_t*)cm,
                                             rs, cs, S1, S2t);

    // contexts (paired; deferred normalization in epilogue)
    k_ctx<<<dim3(6, 4, 128), 256, KN_SMEM>>>(S1, S2t, bp_, ap, rs, cs, beta, alpha);

    // compare + aggregate (paired)
    k_cmp<<<dim3(6, 256, 2), 256, KN_SMEM>>>(ap, bp_, beta, alpha, hWg, bg, a_mask, b_mask, out);
}

// round 11
// speedup vs baseline: 1.0007x; 1.0007x over previous
#include <cuda_runtime.h>
#include <cuda_fp16.h>
#include <stdint.h>
#include <math.h>

// Problem constants
#define BB 64
#define LL 512
#define DD 768
#define HH 768

static const int    M_ROWS = BB * LL;                  // 32768
static const size_t PLH = (size_t)BB * LL * HH;        // 25165824
static const size_t ALL = (size_t)BB * LL * LL;        // 16777216

__device__ __align__(16) float g_scratch[6 * 25165824ULL + 3 * 16777216ULL + 4 * 32768ULL + 2359296ULL];

// ---------------------------------------------------------------------------
// helpers
// ---------------------------------------------------------------------------
__device__ __forceinline__ void cp16(void* s, const void* g) {
    uint32_t sa = (uint32_t)__cvta_generic_to_shared(s);
    asm volatile("cp.async.cg.shared.global [%0], [%1], 16;" :: "r"(sa), "l"(g));
}
__device__ __forceinline__ void cp_commit() { asm volatile("cp.async.commit_group;"); }
__device__ __forceinline__ void cp_wait1()  { asm volatile("cp.async.wait_group 1;"); }

__device__ __forceinline__ void ldsm_x4(uint32_t* r, uint32_t addr) {
    asm volatile("ldmatrix.sync.aligned.m8n8.x4.shared.b16 {%0,%1,%2,%3}, [%4];"
        : "=r"(r[0]), "=r"(r[1]), "=r"(r[2]), "=r"(r[3]) : "r"(addr));
}
__device__ __forceinline__ void ldsm_x4t(uint32_t* r, uint32_t addr) {
    asm volatile("ldmatrix.sync.aligned.m8n8.x4.trans.shared.b16 {%0,%1,%2,%3}, [%4];"
        : "=r"(r[0]), "=r"(r[1]), "=r"(r[2]), "=r"(r[3]) : "r"(addr));
}
__device__ __forceinline__ void mma16(float* c, const uint32_t* a, const uint32_t* b) {
    asm volatile(
        "mma.sync.aligned.m16n8k16.row.col.f32.f16.f16.f32 "
        "{%0,%1,%2,%3},{%4,%5,%6,%7},{%8,%9},{%0,%1,%2,%3};"
        : "+f"(c[0]), "+f"(c[1]), "+f"(c[2]), "+f"(c[3])
        : "r"(a[0]), "r"(a[1]), "r"(a[2]), "r"(a[3]), "r"(b[0]), "r"(b[1]));
}

// monotone float<->uint encoding for atomicMax on floats of any sign
__device__ __forceinline__ uint32_t encf(float f) {
    uint32_t u = __float_as_uint(f);
    return u ^ (uint32_t)(((int32_t)u >> 31) | 0x80000000);
}
__device__ __forceinline__ float decf(uint32_t u) {
    u = (u & 0x80000000u) ? (u ^ 0x80000000u) : ~u;
    return __uint_as_float(u);
}

// SMEM staging (BK = 64, 3 stages):
//  A tile: [128][72] halves, pitch 144 B, stage = 18432 B  (conflict-free ldmatrix)
//  B KN:   [64][136] halves, pitch 272 B, stage = 17408 B
//  B NT:   same layout as A
#define A_STG_B 18432u
#define B_STG_B 17408u
#define A_STG_H 9216
#define B_STG_H 8704

#define COMPUTE64_KN(buf)                                                      \
    _Pragma("unroll")                                                          \
    for (int ks = 0; ks < 4; ks++) {                                           \
        uint32_t af[4][4], bt0[4], bt1[4];                                     \
        _Pragma("unroll")                                                      \
        for (int fm = 0; fm < 4; fm++)                                         \
            ldsm_x4(af[fm], a_addr + (buf) * A_STG_B + ks * 32u + fm * 2304u); \
        ldsm_x4t(bt0, b_addr + (buf) * B_STG_B + ks * 4352u);                  \
        ldsm_x4t(bt1, b_addr + (buf) * B_STG_B + ks * 4352u + 32u);            \
        uint32_t bf[4][2] = {{bt0[0], bt0[1]}, {bt0[2], bt0[3]},               \
                             {bt1[0], bt1[1]}, {bt1[2], bt1[3]}};              \
        _Pragma("unroll")                                                      \
        for (int fm = 0; fm < 4; fm++)                                         \
            _Pragma("unroll")                                                  \
            for (int fn = 0; fn < 4; fn++)                                     \
                mma16(acc[fm][fn], af[fm], bf[fn]);                            \
    }

#define COMPUTE64_NT(buf)                                                      \
    _Pragma("unroll")                                                          \
    for (int ks = 0; ks < 4; ks++) {                                           \
        uint32_t af[4][4], bt0[4], bt1[4];                                     \
        _Pragma("unroll")                                                      \
        for (int fm = 0; fm < 4; fm++)                                         \
            ldsm_x4(af[fm], a_addr + (buf) * A_STG_B + ks * 32u + fm * 2304u); \
        ldsm_x4(bt0, bn_addr + (buf) * A_STG_B + ks * 32u);                    \
        ldsm_x4(bt1, bn_addr + (buf) * A_STG_B + ks * 32u + 2304u);            \
        uint32_t bf[4][2] = {{bt0[0], bt0[2]}, {bt0[1], bt0[3]},               \
                             {bt1[0], bt1[2]}, {bt1[1], bt1[3]}};              \
        _Pragma("unroll")                                                      \
        for (int fm = 0; fm < 4; fm++)                                         \
            _Pragma("unroll")                                                  \
            for (int fn = 0; fn < 4; fn++)                                     \
                mma16(acc[fm][fn], af[fm], bf[fn]);                            \
    }

#define LANE_SETUP                                                             \
    const int t = threadIdx.x;                                                 \
    const int w = t >> 5, l = t & 31, g = l >> 2, q = l & 3;                   \
    const int wm = w >> 2, wn = w & 3;

#define A_ADDR_EXPR (uint32_t)(((wm * 64 + (l & 7) + ((l & 8) ? 8 : 0)) * 72 + ((l & 16) ? 8 : 0)) << 1)
#define B_ADDR_EXPR (uint32_t)((((l & 7) + ((l & 8) ? 8 : 0)) * 136 + wn * 32 + ((l & 16) ? 8 : 0)) << 1)
#define BN_ADDR_EXPR (uint32_t)(((wn * 32 + (l & 7) + ((l & 8) ? 8 : 0)) * 72 + ((l & 16) ? 8 : 0)) << 1)

static const int KN_SMEM = 3 * (A_STG_B + B_STG_B);   // 107520
static const int NT_SMEM = 3 * 2 * A_STG_B;           // 110592

// 3-stage pipeline over BK=64 stages
#define PIPE3_PROLOG()                                                         \
    LOADT(0, 0);  cp_commit();                                                 \
    LOADT(1, 64); cp_commit();

#define PIPE3_BODY(COMPUTE)                                                    \
    {                                                                          \
        int buf = 0, ldst = 2;                                                 \
        for (int kt = 0; kt < nt; kt++) {                                      \
            cp_wait1();                                                        \
            __syncthreads();                                                   \
            if (kt + 2 < nt) { LOADT(ldst, (kt + 2) * 64); }                   \
            cp_commit();                                                       \
            COMPUTE(buf);                                                      \
            if (++buf == 3) buf = 0;                                           \
            if (++ldst == 3) ldst = 0;                                         \
        }                                                                      \
    }

// ---------------------------------------------------------------------------
// converts
// ---------------------------------------------------------------------------
__global__ void k_cvth2(const float* __restrict__ s0, const float* __restrict__ s1,
                        __half* __restrict__ d0, __half* __restrict__ d1, int n)
{
    const float* src = blockIdx.z ? s1 : s0;
    __half* dst = blockIdx.z ? d1 : d0;
    int i = (blockIdx.x * blockDim.x + threadIdx.x) * 4;
    if (i < n) {
        float4 v = *(const float4*)(src + i);
        *(half2*)(dst + i)     = __floats2half2_rn(v.x, v.y);
        *(half2*)(dst + i + 2) = __floats2half2_rn(v.z, v.w);
    }
}
__global__ void k_cvtw(const float* __restrict__ w0, const float* __restrict__ w1,
                       const float* __restrict__ w2,
                       __half* __restrict__ d0, __half* __restrict__ d1, __half* __restrict__ d2)
{
    int z = blockIdx.z;
    const float* src = (z == 0) ? w0 : (z == 1 ? w1 : w2);
    __half* dst = (z == 0) ? d0 : (z == 1 ? d1 : d2);
    int n = (z == 2) ? 2 * HH * HH : DD * HH;
    int i = (blockIdx.x * blockDim.x + threadIdx.x) * 4;
    if (i < n) {
        float4 v = *(const float4*)(src + i);
        *(half2*)(dst + i)     = __floats2half2_rn(v.x, v.y);
        *(half2*)(dst + i + 2) = __floats2half2_rn(v.z, v.w);
    }
}

// ---------------------------------------------------------------------------
// paired proj / attend-F: C = half(relu(A @ W + bias) * mask)   (z selects a/b)
// ---------------------------------------------------------------------------
__global__ __launch_bounds__(256, 2) void k_proj(
    const __half* __restrict__ Aa, const __half* __restrict__ Ab,
    const __half* __restrict__ W, const float* __restrict__ bias,
    const int* __restrict__ ma, const int* __restrict__ mb,
    __half* __restrict__ Ca, __half* __restrict__ Cb, int K)
{
    extern __shared__ __half sm[];
    __half* smA = sm;
    __half* smB = sm + 3 * A_STG_H;
    LANE_SETUP
    const __half* A = blockIdx.z ? Ab : Aa;
    const int* mask = blockIdx.z ? mb : ma;
    __half* C = blockIdx.z ? Cb : Ca;
    const int m0 = blockIdx.y * 128, n0 = blockIdx.x * 128;
    const uint32_t a_base = (uint32_t)__cvta_generic_to_shared(smA);
    const uint32_t b_base = (uint32_t)__cvta_generic_to_shared(smB);
    const uint32_t a_addr = a_base + A_ADDR_EXPR;
    const uint32_t b_addr = b_base + B_ADDR_EXPR;
    float acc[4][4][4] = {};
    const int nt = K / 64;
#define LOADT(st, k0)                                                                       \
    do {                                                                                    \
        _Pragma("unroll")                                                                   \
        for (int p = 0; p < 4; p++) {                                                       \
            int id = t + p * 256;                                                           \
            int arow = id >> 3, ac = id & 7;                                                \
            cp16(smA + (st) * A_STG_H + arow * 72 + ac * 8,                                 \
                 A + (size_t)(m0 + arow) * K + (k0) + ac * 8);                              \
            int brow = id >> 4, bc = id & 15;                                               \
            cp16(smB + (st) * B_STG_H + brow * 136 + bc * 8,                                \
                 W + (size_t)((k0) + brow) * HH + n0 + bc * 8);                             \
        }                                                                                   \
    } while (0)
    PIPE3_PROLOG()
    PIPE3_BODY(COMPUTE64_KN)
#undef LOADT
    const int mbase = m0 + wm * 64, nbase = n0 + wn * 32;
#pragma unroll
    for (int fm = 0; fm < 4; fm++) {
        int m = mbase + fm * 16 + g;
        float mk0 = mask ? (float)mask[m] : 1.0f;
        float mk1 = mask ? (float)mask[m + 8] : 1.0f;
#pragma unroll
        for (int fn = 0; fn < 4; fn++) {
            int n = nbase + fn * 8 + 2 * q;
            float b0 = bias[n], b1 = bias[n + 1];
            *(half2*)&C[(size_t)m * HH + n] =
                __floats2half2_rn(fmaxf(acc[fm][fn][0] + b0, 0.f) * mk0,
                                  fmaxf(acc[fm][fn][1] + b1, 0.f) * mk0);
            *(half2*)&C[(size_t)(m + 8) * HH + n] =
                __floats2half2_rn(fmaxf(acc[fm][fn][2] + b0, 0.f) * mk1,
                                  fmaxf(acc[fm][fn][3] + b1, 0.f) * mk1);
        }
    }
}

// ---------------------------------------------------------------------------
// att[b,i,j] = Fa[b,i,:] . Fb[b,j,:]  (NT), fp32 out + fused row/col max atomics
// ---------------------------------------------------------------------------
__global__ __launch_bounds__(256, 2) void k_att(
    const __half* __restrict__ Fa, const __half* __restrict__ Fb, float* __restrict__ att,
    uint32_t* __restrict__ rm, uint32_t* __restrict__ cm)
{
    extern __shared__ __half sm[];
    __half* smA = sm;
    __half* smB = sm + 3 * A_STG_H;
    LANE_SETUP
    const int b = blockIdx.z;
    const int m0 = blockIdx.y * 128, n0 = blockIdx.x * 128;
    const __half* Ab = Fa + (size_t)b * LL * HH;
    const __half* Bb = Fb + (size_t)b * LL * HH;
    const uint32_t a_base = (uint32_t)__cvta_generic_to_shared(smA);
    const uint32_t b_base = (uint32_t)__cvta_generic_to_shared(smB);
    const uint32_t a_addr  = a_base + A_ADDR_EXPR;
    const uint32_t bn_addr = b_base + BN_ADDR_EXPR;
    float acc[4][4][4] = {};
    const int nt = HH / 64;
#define LOADT(st, k0)                                                                       \
    do {                                                                                    \
        _Pragma("unroll")                                                                   \
        for (int p = 0; p < 4; p++) {                                                       \
            int id = t + p * 256;                                                           \
            int row = id >> 3, cc = id & 7;                                                 \
            cp16(smA + (st) * A_STG_H + row * 72 + cc * 8,                                  \
                 Ab + (size_t)(m0 + row) * HH + (k0) + cc * 8);                             \
            cp16(smB + (st) * A_STG_H + row * 72 + cc * 8,                                  \
                 Bb + (size_t)(n0 + row) * HH + (k0) + cc * 8);                             \
        }                                                                                   \
    } while (0)
    PIPE3_PROLOG()
    PIPE3_BODY(COMPUTE64_NT)
#undef LOADT
    const int mbase = m0 + wm * 64, nbase = n0 + wn * 32;
#pragma unroll
    for (int fm = 0; fm < 4; fm++) {
        int m = mbase + fm * 16 + g;
#pragma unroll
        for (int fn = 0; fn < 4; fn++) {
            int n = nbase + fn * 8 + 2 * q;
            *(float2*)&att[((size_t)b * LL + m) * LL + n] =
                make_float2(acc[fm][fn][0], acc[fm][fn][1]);
            *(float2*)&att[((size_t)b * LL + m + 8) * LL + n] =
                make_float2(acc[fm][fn][2], acc[fm][fn][3]);
        }
    }
    // fused row maxes -> global atomicMax
#pragma unroll
    for (int fm = 0; fm < 4; fm++) {
        float r0 = acc[fm][0][0], r1 = acc[fm][0][2];
#pragma unroll
        for (int fn = 0; fn < 4; fn++) {
            r0 = fmaxf(r0, fmaxf(acc[fm][fn][0], acc[fm][fn][1]));
            r1 = fmaxf(r1, fmaxf(acc[fm][fn][2], acc[fm][fn][3]));
        }
        r0 = fmaxf(r0, __shfl_xor_sync(0xffffffffu, r0, 1));
        r0 = fmaxf(r0, __shfl_xor_sync(0xffffffffu, r0, 2));
        r1 = fmaxf(r1, __shfl_xor_sync(0xffffffffu, r1, 1));
        r1 = fmaxf(r1, __shfl_xor_sync(0xffffffffu, r1, 2));
        if (q == 0) {
            int m = mbase + fm * 16 + g;
            atomicMax(&rm[b * LL + m], encf(r0));
            atomicMax(&rm[b * LL + m + 8], encf(r1));
        }
    }
    // fused col maxes
#pragma unroll
    for (int fn = 0; fn < 4; fn++) {
        float c0 = acc[0][fn][0], c1 = acc[0][fn][1];
#pragma unroll
        for (int fm = 0; fm < 4; fm++) {
            c0 = fmaxf(c0, fmaxf(acc[fm][fn][0], acc[fm][fn][2]));
            c1 = fmaxf(c1, fmaxf(acc[fm][fn][1], acc[fm][fn][3]));
        }
        c0 = fmaxf(c0, __shfl_xor_sync(0xffffffffu, c0, 4));
        c0 = fmaxf(c0, __shfl_xor_sync(0xffffffffu, c0, 8));
        c0 = fmaxf(c0, __shfl_xor_sync(0xffffffffu, c0, 16));
        c1 = fmaxf(c1, __shfl_xor_sync(0xffffffffu, c1, 4));
        c1 = fmaxf(c1, __shfl_xor_sync(0xffffffffu, c1, 8));
        c1 = fmaxf(c1, __shfl_xor_sync(0xffffffffu, c1, 16));
        if (g == 0) {
            int n = nbase + fn * 8 + 2 * q;
            atomicMax(&cm[b * LL + n], encf(c0));
            atomicMax(&cm[b * LL + n + 1], encf(c1));
        }
    }
}

// ---------------------------------------------------------------------------
// map: att -> S1u [b,i,j], S2tu [b,j,i] (unnormalized, half), accumulates rs, cs
// ---------------------------------------------------------------------------
__global__ void k_map(const float* __restrict__ att,
                      const int* __restrict__ a_mask, const int* __restrict__ b_mask,
                      const uint32_t* __restrict__ rm, const uint32_t* __restrict__ cm,
                      float* __restrict__ rs, float* __restrict__ cs,
                      __half* __restrict__ S1, __half* __restrict__ S2t)
{
    const int bb = blockIdx.z;
    const int i0 = blockIdx.y * 32, j0 = blockIdx.x * 32;
    const int tx = threadIdx.x, ty = threadIdx.y;
    const int tid = ty * 32 + tx;
    __shared__ float rmv[32], ermv[32], amv[32];
    __shared__ float ecm[32], bmv[32];
    __shared__ float s2t_sh[32][33];
    __shared__ float colp[8][32];
    if (tid < 32) {
        float c = decf(cm[bb * LL + j0 + tid]);
        ecm[tid] = __expf(-c);
        bmv[tid] = 768.0f * (float)b_mask[bb * LL + j0 + tid];
    } else if (tid < 64) {
        int r = tid - 32;
        float rf = decf(rm[bb * LL + i0 + r]);
        rmv[r] = rf;
        ermv[r] = __expf(rf);
        amv[r] = (float)a_mask[bb * LL + i0 + r];
    }
    __syncthreads();
    float colsum = 0.f;
    for (int r = ty; r < 32; r += 8) {
        const int i = i0 + r;
        float a = att[((size_t)bb * LL + i) * LL + j0 + tx];
        float E = __expf(a - rmv[r]) * (amv[r] * bmv[tx]);
        S1[((size_t)bb * LL + i) * LL + j0 + tx] = __float2half_rn(E);
        float s2 = E * ermv[r] * ecm[tx];
        s2t_sh[tx][r] = s2;
        colsum += s2;
        float rsum = E;
#pragma unroll
        for (int o = 16; o > 0; o >>= 1) rsum += __shfl_xor_sync(0xffffffffu, rsum, o);
        if (tx == 0) atomicAdd(&rs[bb * LL + i], rsum);
    }
    colp[ty][tx] = colsum;
    __syncthreads();
    if (ty == 0) {
        float c = 0.f;
#pragma unroll
        for (int k = 0; k < 8; k++) c += colp[k][tx];
        atomicAdd(&cs[bb * LL + j0 + tx], c);
    }
    for (int r = ty; r < 32; r += 8)
        S2t[((size_t)bb * LL + j0 + r) * LL + i0 + tx] = __float2half_rn(s2t_sh[r][tx]);
}

// ---------------------------------------------------------------------------
// paired ctx (NN, K=512): deferred softmax normalization in epilogue
// ---------------------------------------------------------------------------
__global__ __launch_bounds__(256, 2) void k_ctx(
    const __half* __restrict__ Sa, const __half* __restrict__ Sb,
    const __half* __restrict__ Pa, const __half* __restrict__ Pb,
    const float* __restrict__ sca, const float* __restrict__ scb,
    __half* __restrict__ Ca, __half* __restrict__ Cb)
{
    extern __shared__ __half sm[];
    __half* smA = sm;
    __half* smB = sm + 3 * A_STG_H;
    LANE_SETUP
    const int pair = blockIdx.z >> 6;
    const int b = blockIdx.z & 63;
    const __half* S = pair ? Sb : Sa;
    const __half* P = pair ? Pb : Pa;
    const float* sc = pair ? scb : sca;
    __half* C = pair ? Cb : Ca;
    const int m0 = blockIdx.y * 128, n0 = blockIdx.x * 128;
    const __half* Abp = S + (size_t)b * LL * LL;
    const __half* Bbp = P + (size_t)b * LL * HH;
    const uint32_t a_base = (uint32_t)__cvta_generic_to_shared(smA);
    const uint32_t b_base = (uint32_t)__cvta_generic_to_shared(smB);
    const uint32_t a_addr = a_base + A_ADDR_EXPR;
    const uint32_t b_addr = b_base + B_ADDR_EXPR;
    float acc[4][4][4] = {};
    const int nt = LL / 64;
#define LOADT(st, k0)                                                                       \
    do {                                                                                    \
        _Pragma("unroll")                                                                   \
        for (int p = 0; p < 4; p++) {                                                       \
            int id = t + p * 256;                                                           \
            int arow = id >> 3, ac = id & 7;                                                \
            cp16(smA + (st) * A_STG_H + arow * 72 + ac * 8,                                 \
                 Abp + (size_t)(m0 + arow) * LL + (k0) + ac * 8);                           \
            int brow = id >> 4, bc = id & 15;                                               \
            cp16(smB + (st) * B_STG_H + brow * 136 + bc * 8,                                \
                 Bbp + (size_t)((k0) + brow) * HH + n0 + bc * 8);                           \
        }                                                                                   \
    } while (0)
    PIPE3_PROLOG()
    PIPE3_BODY(COMPUTE64_KN)
#undef LOADT
    const int mbase = m0 + wm * 64, nbase = n0 + wn * 32;
#pragma unroll
    for (int fm = 0; fm < 4; fm++) {
        int m = mbase + fm * 16 + g;
        float s0 = 1.0f / (sc[b * LL + m] + 1e-8f);
        float s1v = 1.0f / (sc[b * LL + m + 8] + 1e-8f);
#pragma unroll
        for (int fn = 0; fn < 4; fn++) {
            int n = nbase + fn * 8 + 2 * q;
            *(half2*)&C[((size_t)b * LL + m) * HH + n] =
                __floats2half2_rn(acc[fm][fn][0] * s0, acc[fm][fn][1] * s0);
            *(half2*)&C[((size_t)b * LL + m + 8) * HH + n] =
                __floats2half2_rn(acc[fm][fn][2] * s1v, acc[fm][fn][3] * s1v);
        }
    }
}

// ---------------------------------------------------------------------------
// paired compare + aggregate
// ---------------------------------------------------------------------------
__global__ __launch_bounds__(256, 2) void k_cmp(
    const __half* __restrict__ Pa, const __half* __restrict__ Pb,
    const __half* __restrict__ Xa, const __half* __restrict__ Xb,
    const __half* __restrict__ Wg, const float* __restrict__ bg,
    const int* __restrict__ ma, const int* __restrict__ mb,
    float* __restrict__ out)
{
    extern __shared__ __half sm[];
    __half* smA = sm;
    __half* smB = sm + 3 * A_STG_H;
    __shared__ float red_s[128][2];
    __shared__ float red_m[128][2];
    LANE_SETUP
    const int z = blockIdx.z;
    const __half* P = z ? Pb : Pa;
    const __half* CTX = z ? Xb : Xa;
    const int* mask = z ? mb : ma;
    const int sumoff = z ? 768 : 0, maxoff = z ? 2304 : 1536;
    const int m0 = blockIdx.y * 128, n0 = blockIdx.x * 128;
    const uint32_t a_base = (uint32_t)__cvta_generic_to_shared(smA);
    const uint32_t b_base = (uint32_t)__cvta_generic_to_shared(smB);
    const uint32_t a_addr = a_base + A_ADDR_EXPR;
    const uint32_t b_addr = b_base + B_ADDR_EXPR;
    float acc[4][4][4] = {};
    const int nt = (2 * HH) / 64;  // 24
#define LOADT(st, k0)                                                                       \
    do {                                                                                    \
        const __half* Asrc = ((k0) < HH) ? P : CTX;                                         \
        const int kk0 = ((k0) < HH) ? (k0) : ((k0) - HH);                                   \
        _Pragma("unroll")                                                                   \
        for (int p = 0; p < 4; p++) {                                                       \
            int id = t + p * 256;                                                           \
            int arow = id >> 3, ac = id & 7;                                                \
            cp16(smA + (st) * A_STG_H + arow * 72 + ac * 8,                                 \
                 Asrc + (size_t)(m0 + arow) * HH + kk0 + ac * 8);                           \
            int brow = id >> 4, bc = id & 15;                                               \
            cp16(smB + (st) * B_STG_H + brow * 136 + bc * 8,                                \
                 Wg + (size_t)((k0) + brow) * HH + n0 + bc * 8);                            \
        }                                                                                   \
    } while (0)
    PIPE3_PROLOG()
    PIPE3_BODY(COMPUTE64_KN)
#undef LOADT
    const int mbase = m0 + wm * 64, nbase = n0 + wn * 32;
    float psum[4][2] = {}, pmax[4][2] = {};
#pragma unroll
    for (int fm = 0; fm < 4; fm++) {
        int m = mbase + fm * 16 + g;
        float mk0 = (float)mask[m];
        float mk1 = (float)mask[m + 8];
#pragma unroll
        for (int fn = 0; fn < 4; fn++) {
            int n = nbase + fn * 8 + 2 * q;
            float b0 = bg[n], b1 = bg[n + 1];
            float v00 = fmaxf(acc[fm][fn][0] + b0, 0.f) * mk0;
            float v01 = fmaxf(acc[fm][fn][1] + b1, 0.f) * mk0;
            float v10 = fmaxf(acc[fm][fn][2] + b0, 0.f) * mk1;
            float v11 = fmaxf(acc[fm][fn][3] + b1, 0.f) * mk1;
            psum[fn][0] += v00 + v10;
            psum[fn][1] += v01 + v11;
            pmax[fn][0] = fmaxf(pmax[fn][0], fmaxf(v00, v10));
            pmax[fn][1] = fmaxf(pmax[fn][1], fmaxf(v01, v11));
        }
    }
#pragma unroll
    for (int fn = 0; fn < 4; fn++)
#pragma unroll
        for (int e = 0; e < 2; e++) {
#pragma unroll
            for (int o = 4; o < 32; o <<= 1) {
                psum[fn][e] += __shfl_xor_sync(0xffffffffu, psum[fn][e], o);
                pmax[fn][e] = fmaxf(pmax[fn][e], __shfl_xor_sync(0xffffffffu, pmax[fn][e], o));
            }
        }
    if (l < 4) {
#pragma unroll
        for (int fn = 0; fn < 4; fn++)
#pragma unroll
            for (int e = 0; e < 2; e++) {
                int c = wn * 32 + fn * 8 + 2 * q + e;
                red_s[c][wm] = psum[fn][e];
                red_m[c][wm] = pmax[fn][e];
            }
    }
    __syncthreads();
    if (t < 128) {
        const int bb = m0 >> 9;
        float s = red_s[t][0] + red_s[t][1];
        float mx = fmaxf(red_m[t][0], red_m[t][1]);
        atomicAdd(&out[bb * 3072 + sumoff + n0 + t], s);
        atomicMax((int*)&out[bb * 3072 + maxoff + n0 + t], __float_as_int(mx));
    }
}

// zero out + stats accumulators (rm/cm encoded maxes, rs/cs sums)
__global__ void k_zero(float* __restrict__ out, float* __restrict__ stats)
{
    int i = blockIdx.x * blockDim.x + threadIdx.x;
    if (i < BB * 4 * HH) out[i] = 0.0f;
    if (i < 4 * M_ROWS) stats[i] = 0.0f;
}

extern "C" void kernel_launch(void* const* d_in, const int* in_sizes, int n_in,
                              void* d_out, int out_size)
{
    const float* a_embeds = (const float*)d_in[0];
    const float* b_embeds = (const float*)d_in[1];
    const int*   a_mask   = (const int*)d_in[2];
    const int*   b_mask   = (const int*)d_in[3];
    const float* Wp = (const float*)d_in[4];
    const float* bp = (const float*)d_in[5];
    const float* Wf = (const float*)d_in[6];
    const float* bf = (const float*)d_in[7];
    const float* Wg = (const float*)d_in[8];
    const float* bg = (const float*)d_in[9];
    float* out = (float*)d_out;

    float* base = nullptr;
    cudaGetSymbolAddress((void**)&base, g_scratch);
    float* att = base;
    float* rm  = att + ALL;          // encoded uint maxes
    float* cm  = rm + M_ROWS;
    float* rs  = cm + M_ROWS;
    float* cs  = rs + M_ROWS;
    __half* ah    = (__half*)(cs + M_ROWS);
    __half* bh    = ah + PLH;
    __half* ap    = bh + PLH;
    __half* bp_   = ap + PLH;
    __half* Fa    = bp_ + PLH;
    __half* Fb    = Fa + PLH;
    __half* beta  = Fb + PLH;
    __half* alpha = beta + PLH;
    __half* S1    = alpha + PLH;
    __half* S2t   = S1 + ALL;
    __half* hWp   = S2t + ALL;
    __half* hWf   = hWp + DD * HH;
    __half* hWg   = hWf + HH * HH;

    cudaFuncSetAttribute(k_proj, cudaFuncAttributeMaxDynamicSharedMemorySize, KN_SMEM);
    cudaFuncSetAttribute(k_att,  cudaFuncAttributeMaxDynamicSharedMemorySize, NT_SMEM);
    cudaFuncSetAttribute(k_ctx,  cudaFuncAttributeMaxDynamicSharedMemorySize, KN_SMEM);
    cudaFuncSetAttribute(k_cmp,  cudaFuncAttributeMaxDynamicSharedMemorySize, KN_SMEM);

    k_zero<<<(BB * 4 * HH + 1023) / 1024, 1024>>>(out, rm);

    // fp32 -> fp16 conversions
    k_cvth2<<<dim3((int)((PLH / 4 + 255) / 256), 1, 2), 256>>>(a_embeds, b_embeds, ah, bh, (int)PLH);
    k_cvtw<<<dim3((2 * HH * HH / 4 + 255) / 256, 1, 3), 256>>>(Wp, Wf, Wg, hWp, hWf, hWg);

    // shared projection FFN (paired a/b)
    k_proj<<<dim3(6, 256, 2), 256, KN_SMEM>>>(ah, bh, hWp, bp, nullptr, nullptr, ap, bp_, DD);

    // attend features (paired, relu + mask)
    k_proj<<<dim3(6, 256, 2), 256, KN_SMEM>>>(ap, bp_, hWf, bf, a_mask, b_mask, Fa, Fb, HH);

    // attention scores + fused row/col max
    k_att<<<dim3(4, 4, 64), 256, NT_SMEM>>>(Fa, Fb, att, (uint32_t*)rm, (uint32_t*)cm);

    // map: unnormalized softmax numerators + sum accumulation
    k_map<<<dim3(16, 16, 64), dim3(32, 8)>>>(att, a_mask, b_mask,
                                             (const uint32_t*)rm, (const uint32_t*)cm,
                                             rs, cs, S1, S2t);

    // contexts (paired; deferred normalization in epilogue)
    k_ctx<<<dim3(6, 4, 128), 256, KN_SMEM>>>(S1, S2t, bp_, ap, rs, cs, beta, alpha);

    // compare + aggregate (paired)
    k_cmp<<<dim3(6, 256, 2), 256, KN_SMEM>>>(ap, bp_, beta, alpha, hWg, bg, a_mask, b_mask, out);
}

// round 12
// speedup vs baseline: 1.0020x; 1.0013x over previous
#include <cuda_runtime.h>
#include <cuda_fp16.h>
#include <stdint.h>
#include <math.h>

// Problem constants
#define BB 64
#define LL 512
#define DD 768
#define HH 768

static const int    M_ROWS = BB * LL;                  // 32768
static const size_t PLH = (size_t)BB * LL * HH;        // 25165824
static const size_t ALL = (size_t)BB * LL * LL;        // 16777216

__device__ __align__(16) float g_scratch[6 * 25165824ULL + 3 * 16777216ULL + 4 * 32768ULL + 2359296ULL];

// ---------------------------------------------------------------------------
// helpers
// ---------------------------------------------------------------------------
__device__ __forceinline__ void cp16(void* s, const void* g) {
    uint32_t sa = (uint32_t)__cvta_generic_to_shared(s);
    asm volatile("cp.async.cg.shared.global [%0], [%1], 16;" :: "r"(sa), "l"(g));
}
__device__ __forceinline__ void cp_commit() { asm volatile("cp.async.commit_group;"); }
__device__ __forceinline__ void cp_wait1()  { asm volatile("cp.async.wait_group 1;"); }

__device__ __forceinline__ void ldsm_x4(uint32_t* r, uint32_t addr) {
    asm volatile("ldmatrix.sync.aligned.m8n8.x4.shared.b16 {%0,%1,%2,%3}, [%4];"
        : "=r"(r[0]), "=r"(r[1]), "=r"(r[2]), "=r"(r[3]) : "r"(addr));
}
__device__ __forceinline__ void ldsm_x4t(uint32_t* r, uint32_t addr) {
    asm volatile("ldmatrix.sync.aligned.m8n8.x4.trans.shared.b16 {%0,%1,%2,%3}, [%4];"
        : "=r"(r[0]), "=r"(r[1]), "=r"(r[2]), "=r"(r[3]) : "r"(addr));
}
__device__ __forceinline__ void mma16(float* c, const uint32_t* a, const uint32_t* b) {
    asm volatile(
        "mma.sync.aligned.m16n8k16.row.col.f32.f16.f16.f32 "
        "{%0,%1,%2,%3},{%4,%5,%6,%7},{%8,%9},{%0,%1,%2,%3};"
        : "+f"(c[0]), "+f"(c[1]), "+f"(c[2]), "+f"(c[3])
        : "r"(a[0]), "r"(a[1]), "r"(a[2]), "r"(a[3]), "r"(b[0]), "r"(b[1]));
}

// monotone float<->uint encoding for atomicMax on floats of any sign
__device__ __forceinline__ uint32_t encf(float f) {
    uint32_t u = __float_as_uint(f);
    return u ^ (uint32_t)(((int32_t)u >> 31) | 0x80000000);
}
__device__ __forceinline__ float decf(uint32_t u) {
    u = (u & 0x80000000u) ? (u ^ 0x80000000u) : ~u;
    return __uint_as_float(u);
}

// SMEM staging (BK = 64, 3 stages):
//  A tile: [128][72] halves, pitch 144 B, stage = 18432 B  (conflict-free ldmatrix)
//  B KN:   [64][136] halves, pitch 272 B, stage = 17408 B
//  B NT:   same layout as A
#define A_STG_B 18432u
#define B_STG_B 17408u
#define A_STG_H 9216
#define B_STG_H 8704

#define COMPUTE64_KN(buf)                                                      \
    _Pragma("unroll")                                                          \
    for (int ks = 0; ks < 4; ks++) {                                           \
        uint32_t af[4][4], bt0[4], bt1[4];                                     \
        _Pragma("unroll")                                                      \
        for (int fm = 0; fm < 4; fm++)                                         \
            ldsm_x4(af[fm], a_addr + (buf) * A_STG_B + ks * 32u + fm * 2304u); \
        ldsm_x4t(bt0, b_addr + (buf) * B_STG_B + ks * 4352u);                  \
        ldsm_x4t(bt1, b_addr + (buf) * B_STG_B + ks * 4352u + 32u);            \
        uint32_t bf[4][2] = {{bt0[0], bt0[1]}, {bt0[2], bt0[3]},               \
                             {bt1[0], bt1[1]}, {bt1[2], bt1[3]}};              \
        _Pragma("unroll")                                                      \
        for (int fm = 0; fm < 4; fm++)                                         \
            _Pragma("unroll")                                                  \
            for (int fn = 0; fn < 4; fn++)                                     \
                mma16(acc[fm][fn], af[fm], bf[fn]);                            \
    }

#define COMPUTE64_NT(buf)                                                      \
    _Pragma("unroll")                                                          \
    for (int ks = 0; ks < 4; ks++) {                                           \
        uint32_t af[4][4], bt0[4], bt1[4];                                     \
        _Pragma("unroll")                                                      \
        for (int fm = 0; fm < 4; fm++)                                         \
            ldsm_x4(af[fm], a_addr + (buf) * A_STG_B + ks * 32u + fm * 2304u); \
        ldsm_x4(bt0, bn_addr + (buf) * A_STG_B + ks * 32u);                    \
        ldsm_x4(bt1, bn_addr + (buf) * A_STG_B + ks * 32u + 2304u);            \
        uint32_t bf[4][2] = {{bt0[0], bt0[2]}, {bt0[1], bt0[3]},               \
                             {bt1[0], bt1[2]}, {bt1[1], bt1[3]}};              \
        _Pragma("unroll")                                                      \
        for (int fm = 0; fm < 4; fm++)                                         \
            _Pragma("unroll")                                                  \
            for (int fn = 0; fn < 4; fn++)                                     \
                mma16(acc[fm][fn], af[fm], bf[fn]);                            \
    }

#define LANE_SETUP                                                             \
    const int t = threadIdx.x;                                                 \
    const int w = t >> 5, l = t & 31, g = l >> 2, q = l & 3;                   \
    const int wm = w >> 2, wn = w & 3;

#define A_ADDR_EXPR (uint32_t)(((wm * 64 + (l & 7) + ((l & 8) ? 8 : 0)) * 72 + ((l & 16) ? 8 : 0)) << 1)
#define B_ADDR_EXPR (uint32_t)((((l & 7) + ((l & 8) ? 8 : 0)) * 136 + wn * 32 + ((l & 16) ? 8 : 0)) << 1)
#define BN_ADDR_EXPR (uint32_t)(((wn * 32 + (l & 7) + ((l & 8) ? 8 : 0)) * 72 + ((l & 16) ? 8 : 0)) << 1)

static const int KN_SMEM = 3 * (A_STG_B + B_STG_B);   // 107520
static const int NT_SMEM = 3 * 2 * A_STG_B;           // 110592

// 3-stage pipeline over BK=64 stages
#define PIPE3_PROLOG()                                                         \
    LOADT(0, 0);  cp_commit();                                                 \
    LOADT(1, 64); cp_commit();

#define PIPE3_BODY(COMPUTE)                                                    \
    {                                                                          \
        int buf = 0, ldst = 2;                                                 \
        for (int kt = 0; kt < nt; kt++) {                                      \
            cp_wait1();                                                        \
            __syncthreads();                                                   \
            if (kt + 2 < nt) { LOADT(ldst, (kt + 2) * 64); }                   \
            cp_commit();                                                       \
            COMPUTE(buf);                                                      \
            if (++buf == 3) buf = 0;                                           \
            if (++ldst == 3) ldst = 0;                                         \
        }                                                                      \
    }

// ---------------------------------------------------------------------------
// converts
// ---------------------------------------------------------------------------
__global__ void k_cvth2(const float* __restrict__ s0, const float* __restrict__ s1,
                        __half* __restrict__ d0, __half* __restrict__ d1, int n)
{
    const float* src = blockIdx.z ? s1 : s0;
    __half* dst = blockIdx.z ? d1 : d0;
    int i = (blockIdx.x * blockDim.x + threadIdx.x) * 4;
    if (i < n) {
        float4 v = *(const float4*)(src + i);
        *(half2*)(dst + i)     = __floats2half2_rn(v.x, v.y);
        *(half2*)(dst + i + 2) = __floats2half2_rn(v.z, v.w);
    }
}
__global__ void k_cvtw(const float* __restrict__ w0, const float* __restrict__ w1,
                       const float* __restrict__ w2,
                       __half* __restrict__ d0, __half* __restrict__ d1, __half* __restrict__ d2)
{
    int z = blockIdx.z;
    const float* src = (z == 0) ? w0 : (z == 1 ? w1 : w2);
    __half* dst = (z == 0) ? d0 : (z == 1 ? d1 : d2);
    int n = (z == 2) ? 2 * HH * HH : DD * HH;
    int i = (blockIdx.x * blockDim.x + threadIdx.x) * 4;
    if (i < n) {
        float4 v = *(const float4*)(src + i);
        *(half2*)(dst + i)     = __floats2half2_rn(v.x, v.y);
        *(half2*)(dst + i + 2) = __floats2half2_rn(v.z, v.w);
    }
}

// ---------------------------------------------------------------------------
// paired proj / attend-F: C = half(relu(A @ W + bias) * mask)   (z selects a/b)
// ---------------------------------------------------------------------------
__global__ __launch_bounds__(256, 2) void k_proj(
    const __half* __restrict__ Aa, const __half* __restrict__ Ab,
    const __half* __restrict__ W, const float* __restrict__ bias,
    const int* __restrict__ ma, const int* __restrict__ mb,
    __half* __restrict__ Ca, __half* __restrict__ Cb, int K)
{
    extern __shared__ __half sm[];
    __half* smA = sm;
    __half* smB = sm + 3 * A_STG_H;
    LANE_SETUP
    const __half* A = blockIdx.z ? Ab : Aa;
    const int* mask = blockIdx.z ? mb : ma;
    __half* C = blockIdx.z ? Cb : Ca;
    const int m0 = blockIdx.y * 128, n0 = blockIdx.x * 128;
    const uint32_t a_base = (uint32_t)__cvta_generic_to_shared(smA);
    const uint32_t b_base = (uint32_t)__cvta_generic_to_shared(smB);
    const uint32_t a_addr = a_base + A_ADDR_EXPR;
    const uint32_t b_addr = b_base + B_ADDR_EXPR;
    float acc[4][4][4] = {};
    const int nt = K / 64;
#define LOADT(st, k0)                                                                       \
    do {                                                                                    \
        _Pragma("unroll")                                                                   \
        for (int p = 0; p < 4; p++) {                                                       \
            int id = t + p * 256;                                                           \
            int arow = id >> 3, ac = id & 7;                                                \
            cp16(smA + (st) * A_STG_H + arow * 72 + ac * 8,                                 \
                 A + (size_t)(m0 + arow) * K + (k0) + ac * 8);                              \
            int brow = id >> 4, bc = id & 15;                                               \
            cp16(smB + (st) * B_STG_H + brow * 136 + bc * 8,                                \
                 W + (size_t)((k0) + brow) * HH + n0 + bc * 8);                             \
        }                                                                                   \
    } while (0)
    PIPE3_PROLOG()
    PIPE3_BODY(COMPUTE64_KN)
#undef LOADT
    const int mbase = m0 + wm * 64, nbase = n0 + wn * 32;
#pragma unroll
    for (int fm = 0; fm < 4; fm++) {
        int m = mbase + fm * 16 + g;
        float mk0 = mask ? (float)mask[m] : 1.0f;
        float mk1 = mask ? (float)mask[m + 8] : 1.0f;
#pragma unroll
        for (int fn = 0; fn < 4; fn++) {
            int n = nbase + fn * 8 + 2 * q;
            float b0 = bias[n], b1 = bias[n + 1];
            *(half2*)&C[(size_t)m * HH + n] =
                __floats2half2_rn(fmaxf(acc[fm][fn][0] + b0, 0.f) * mk0,
                                  fmaxf(acc[fm][fn][1] + b1, 0.f) * mk0);
            *(half2*)&C[(size_t)(m + 8) * HH + n] =
                __floats2half2_rn(fmaxf(acc[fm][fn][2] + b0, 0.f) * mk1,
                                  fmaxf(acc[fm][fn][3] + b1, 0.f) * mk1);
        }
    }
}

// ---------------------------------------------------------------------------
// att[b,i,j] = Fa[b,i,:] . Fb[b,j,:]  (NT), fp32 out + fused row/col max atomics
// ---------------------------------------------------------------------------
__global__ __launch_bounds__(256, 2) void k_att(
    const __half* __restrict__ Fa, const __half* __restrict__ Fb, float* __restrict__ att,
    uint32_t* __restrict__ rm, uint32_t* __restrict__ cm)
{
    extern __shared__ __half sm[];
    __half* smA = sm;
    __half* smB = sm + 3 * A_STG_H;
    LANE_SETUP
    const int b = blockIdx.z;
    const int m0 = blockIdx.y * 128, n0 = blockIdx.x * 128;
    const __half* Ab = Fa + (size_t)b * LL * HH;
    const __half* Bb = Fb + (size_t)b * LL * HH;
    const uint32_t a_base = (uint32_t)__cvta_generic_to_shared(smA);
    const uint32_t b_base = (uint32_t)__cvta_generic_to_shared(smB);
    const uint32_t a_addr  = a_base + A_ADDR_EXPR;
    const uint32_t bn_addr = b_base + BN_ADDR_EXPR;
    float acc[4][4][4] = {};
    const int nt = HH / 64;
#define LOADT(st, k0)                                                                       \
    do {                                                                                    \
        _Pragma("unroll")                                                                   \
        for (int p = 0; p < 4; p++) {                                                       \
            int id = t + p * 256;                                                           \
            int row = id >> 3, cc = id & 7;                                                 \
            cp16(smA + (st) * A_STG_H + row * 72 + cc * 8,                                  \
                 Ab + (size_t)(m0 + row) * HH + (k0) + cc * 8);                             \
            cp16(smB + (st) * A_STG_H + row * 72 + cc * 8,                                  \
                 Bb + (size_t)(n0 + row) * HH + (k0) + cc * 8);                             \
        }                                                                                   \
    } while (0)
    PIPE3_PROLOG()
    PIPE3_BODY(COMPUTE64_NT)
#undef LOADT
    const int mbase = m0 + wm * 64, nbase = n0 + wn * 32;
#pragma unroll
    for (int fm = 0; fm < 4; fm++) {
        int m = mbase + fm * 16 + g;
#pragma unroll
        for (int fn = 0; fn < 4; fn++) {
            int n = nbase + fn * 8 + 2 * q;
            *(float2*)&att[((size_t)b * LL + m) * LL + n] =
                make_float2(acc[fm][fn][0], acc[fm][fn][1]);
            *(float2*)&att[((size_t)b * LL + m + 8) * LL + n] =
                make_float2(acc[fm][fn][2], acc[fm][fn][3]);
        }
    }
    // fused row maxes -> global atomicMax
#pragma unroll
    for (int fm = 0; fm < 4; fm++) {
        float r0 = acc[fm][0][0], r1 = acc[fm][0][2];
#pragma unroll
        for (int fn = 0; fn < 4; fn++) {
            r0 = fmaxf(r0, fmaxf(acc[fm][fn][0], acc[fm][fn][1]));
            r1 = fmaxf(r1, fmaxf(acc[fm][fn][2], acc[fm][fn][3]));
        }
        r0 = fmaxf(r0, __shfl_xor_sync(0xffffffffu, r0, 1));
        r0 = fmaxf(r0, __shfl_xor_sync(0xffffffffu, r0, 2));
        r1 = fmaxf(r1, __shfl_xor_sync(0xffffffffu, r1, 1));
        r1 = fmaxf(r1, __shfl_xor_sync(0xffffffffu, r1, 2));
        if (q == 0) {
            int m = mbase + fm * 16 + g;
            atomicMax(&rm[b * LL + m], encf(r0));
            atomicMax(&rm[b * LL + m + 8], encf(r1));
        }
    }
    // fused col maxes
#pragma unroll
    for (int fn = 0; fn < 4; fn++) {
        float c0 = acc[0][fn][0], c1 = acc[0][fn][1];
#pragma unroll
        for (int fm = 0; fm < 4; fm++) {
            c0 = fmaxf(c0, fmaxf(acc[fm][fn][0], acc[fm][fn][2]));
            c1 = fmaxf(c1, fmaxf(acc[fm][fn][1], acc[fm][fn][3]));
        }
        c0 = fmaxf(c0, __shfl_xor_sync(0xffffffffu, c0, 4));
        c0 = fmaxf(c0, __shfl_xor_sync(0xffffffffu, c0, 8));
        c0 = fmaxf(c0, __shfl_xor_sync(0xffffffffu, c0, 16));
        c1 = fmaxf(c1, __shfl_xor_sync(0xffffffffu, c1, 4));
        c1 = fmaxf(c1, __shfl_xor_sync(0xffffffffu, c1, 8));
        c1 = fmaxf(c1, __shfl_xor_sync(0xffffffffu, c1, 16));
        if (g == 0) {
            int n = nbase + fn * 8 + 2 * q;
            atomicMax(&cm[b * LL + n], encf(c0));
            atomicMax(&cm[b * LL + n + 1], encf(c1));
        }
    }
}

// ---------------------------------------------------------------------------
// map: att -> S1u [b,i,j], S2tu [b,j,i] (unnormalized, half), accumulates rs, cs
// ---------------------------------------------------------------------------
__global__ void k_map(const float* __restrict__ att,
                      const int* __restrict__ a_mask, const int* __restrict__ b_mask,
                      const uint32_t* __restrict__ rm, const uint32_t* __restrict__ cm,
                      float* __restrict__ rs, float* __restrict__ cs,
                      __half* __restrict__ S1, __half* __restrict__ S2t)
{
    const int bb = blockIdx.z;
    const int i0 = blockIdx.y * 32, j0 = blockIdx.x * 32;
    const int tx = threadIdx.x, ty = threadIdx.y;
    const int tid = ty * 32 + tx;
    __shared__ float rmv[32], ermv[32], amv[32];
    __shared__ float ecm[32], bmv[32];
    __shared__ float s2t_sh[32][33];
    __shared__ float colp[8][32];
    if (tid < 32) {
        float c = decf(cm[bb * LL + j0 + tid]);
        ecm[tid] = __expf(-c);
        bmv[tid] = 768.0f * (float)b_mask[bb * LL + j0 + tid];
    } else if (tid < 64) {
        int r = tid - 32;
        float rf = decf(rm[bb * LL + i0 + r]);
        rmv[r] = rf;
        ermv[r] = __expf(rf);
        amv[r] = (float)a_mask[bb * LL + i0 + r];
    }
    __syncthreads();
    float colsum = 0.f;
    for (int r = ty; r < 32; r += 8) {
        const int i = i0 + r;
        float a = att[((size_t)bb * LL + i) * LL + j0 + tx];
        float E = __expf(a - rmv[r]) * (amv[r] * bmv[tx]);
        S1[((size_t)bb * LL + i) * LL + j0 + tx] = __float2half_rn(E);
        float s2 = E * ermv[r] * ecm[tx];
        s2t_sh[tx][r] = s2;
        colsum += s2;
        float rsum = E;
#pragma unroll
        for (int o = 16; o > 0; o >>= 1) rsum += __shfl_xor_sync(0xffffffffu, rsum, o);
        if (tx == 0) atomicAdd(&rs[bb * LL + i], rsum);
    }
    colp[ty][tx] = colsum;
    __syncthreads();
    if (ty == 0) {
        float c = 0.f;
#pragma unroll
        for (int k = 0; k < 8; k++) c += colp[k][tx];
        atomicAdd(&cs[bb * LL + j0 + tx], c);
    }
    for (int r = ty; r < 32; r += 8)
        S2t[((size_t)bb * LL + j0 + r) * LL + i0 + tx] = __float2half_rn(s2t_sh[r][tx]);
}

// ---------------------------------------------------------------------------
// paired ctx (NN, K=512): deferred softmax normalization in epilogue
// ---------------------------------------------------------------------------
__global__ __launch_bounds__(256, 2) void k_ctx(
    const __half* __restrict__ Sa, const __half* __restrict__ Sb,
    const __half* __restrict__ Pa, const __half* __restrict__ Pb,
    const float* __restrict__ sca, const float* __restrict__ scb,
    __half* __restrict__ Ca, __half* __restrict__ Cb)
{
    extern __shared__ __half sm[];
    __half* smA = sm;
    __half* smB = sm + 3 * A_STG_H;
    LANE_SETUP
    const int pair = blockIdx.z >> 6;
    const int b = blockIdx.z & 63;
    const __half* S = pair ? Sb : Sa;
    const __half* P = pair ? Pb : Pa;
    const float* sc = pair ? scb : sca;
    __half* C = pair ? Cb : Ca;
    const int m0 = blockIdx.y * 128, n0 = blockIdx.x * 128;
    const __half* Abp = S + (size_t)b * LL * LL;
    const __half* Bbp = P + (size_t)b * LL * HH;
    const uint32_t a_base = (uint32_t)__cvta_generic_to_shared(smA);
    const uint32_t b_base = (uint32_t)__cvta_generic_to_shared(smB);
    const uint32_t a_addr = a_base + A_ADDR_EXPR;
    const uint32_t b_addr = b_base + B_ADDR_EXPR;
    float acc[4][4][4] = {};
    const int nt = LL / 64;
#define LOADT(st, k0)                                                                       \
    do {                                                                                    \
        _Pragma("unroll")                                                                   \
        for (int p = 0; p < 4; p++) {                                                       \
            int id = t + p * 256;                                                           \
            int arow = id >> 3, ac = id & 7;                                                \
            cp16(smA + (st) * A_STG_H + arow * 72 + ac * 8,                                 \
                 Abp + (size_t)(m0 + arow) * LL + (k0) + ac * 8);                           \
            int brow = id >> 4, bc = id & 15;                                               \
            cp16(smB + (st) * B_STG_H + brow * 136 + bc * 8,                                \
                 Bbp + (size_t)((k0) + brow) * HH + n0 + bc * 8);                           \
        }                                                                                   \
    } while (0)
    PIPE3_PROLOG()
    PIPE3_BODY(COMPUTE64_KN)
#undef LOADT
    const int mbase = m0 + wm * 64, nbase = n0 + wn * 32;
#pragma unroll
    for (int fm = 0; fm < 4; fm++) {
        int m = mbase + fm * 16 + g;
        float s0 = 1.0f / (sc[b * LL + m] + 1e-8f);
        float s1v = 1.0f / (sc[b * LL + m + 8] + 1e-8f);
#pragma unroll
        for (int fn = 0; fn < 4; fn++) {
            int n = nbase + fn * 8 + 2 * q;
            *(half2*)&C[((size_t)b * LL + m) * HH + n] =
                __floats2half2_rn(acc[fm][fn][0] * s0, acc[fm][fn][1] * s0);
            *(half2*)&C[((size_t)b * LL + m + 8) * HH + n] =
                __floats2half2_rn(acc[fm][fn][2] * s1v, acc[fm][fn][3] * s1v);
        }
    }
}

// ---------------------------------------------------------------------------
// paired compare + aggregate
// ---------------------------------------------------------------------------
__global__ __launch_bounds__(256, 2) void k_cmp(
    const __half* __restrict__ Pa, const __half* __restrict__ Pb,
    const __half* __restrict__ Xa, const __half* __restrict__ Xb,
    const __half* __restrict__ Wg, const float* __restrict__ bg,
    const int* __restrict__ ma, const int* __restrict__ mb,
    float* __restrict__ out)
{
    extern __shared__ __half sm[];
    __half* smA = sm;
    __half* smB = sm + 3 * A_STG_H;
    __shared__ float red_s[128][2];
    __shared__ float red_m[128][2];
    LANE_SETUP
    const int z = blockIdx.z;
    const __half* P = z ? Pb : Pa;
    const __half* CTX = z ? Xb : Xa;
    const int* mask = z ? mb : ma;
    const int sumoff = z ? 768 : 0, maxoff = z ? 2304 : 1536;
    const int m0 = blockIdx.y * 128, n0 = blockIdx.x * 128;
    const uint32_t a_base = (uint32_t)__cvta_generic_to_shared(smA);
    const uint32_t b_base = (uint32_t)__cvta_generic_to_shared(smB);
    const uint32_t a_addr = a_base + A_ADDR_EXPR;
    const uint32_t b_addr = b_base + B_ADDR_EXPR;
    float acc[4][4][4] = {};
    const int nt = (2 * HH) / 64;  // 24
#define LOADT(st, k0)                                                                       \
    do {                                                                                    \
        const __half* Asrc = ((k0) < HH) ? P : CTX;                                         \
        const int kk0 = ((k0) < HH) ? (k0) : ((k0) - HH);                                   \
        _Pragma("unroll")                                                                   \
        for (int p = 0; p < 4; p++) {                                                       \
            int id = t + p * 256;                                                           \
            int arow = id >> 3, ac = id & 7;                                                \
            cp16(smA + (st) * A_STG_H + arow * 72 + ac * 8,                                 \
                 Asrc + (size_t)(m0 + arow) * HH + kk0 + ac * 8);                           \
            int brow = id >> 4, bc = id & 15;                                               \
            cp16(smB + (st) * B_STG_H + brow * 136 + bc * 8,                                \
                 Wg + (size_t)((k0) + brow) * HH + n0 + bc * 8);                            \
        }                                                                                   \
    } while (0)
    PIPE3_PROLOG()
    PIPE3_BODY(COMPUTE64_KN)
#undef LOADT
    const int mbase = m0 + wm * 64, nbase = n0 + wn * 32;
    float psum[4][2] = {}, pmax[4][2] = {};
#pragma unroll
    for (int fm = 0; fm < 4; fm++) {
        int m = mbase + fm * 16 + g;
        float mk0 = (float)mask[m];
        float mk1 = (float)mask[m + 8];
#pragma unroll
        for (int fn = 0; fn < 4; fn++) {
            int n = nbase + fn * 8 + 2 * q;
            float b0 = bg[n], b1 = bg[n + 1];
            float v00 = fmaxf(acc[fm][fn][0] + b0, 0.f) * mk0;
            float v01 = fmaxf(acc[fm][fn][1] + b1, 0.f) * mk0;
            float v10 = fmaxf(acc[fm][fn][2] + b0, 0.f) * mk1;
            float v11 = fmaxf(acc[fm][fn][3] + b1, 0.f) * mk1;
            psum[fn][0] += v00 + v10;
            psum[fn][1] += v01 + v11;
            pmax[fn][0] = fmaxf(pmax[fn][0], fmaxf(v00, v10));
            pmax[fn][1] = fmaxf(pmax[fn][1], fmaxf(v01, v11));
        }
    }
#pragma unroll
    for (int fn = 0; fn < 4; fn++)
#pragma unroll
        for (int e = 0; e < 2; e++) {
#pragma unroll
            for (int o = 4; o < 32; o <<= 1) {
                psum[fn][e] += __shfl_xor_sync(0xffffffffu, psum[fn][e], o);
                pmax[fn][e] = fmaxf(pmax[fn][e], __shfl_xor_sync(0xffffffffu, pmax[fn][e], o));
            }
        }
    if (l < 4) {
#pragma unroll
        for (int fn = 0; fn < 4; fn++)
#pragma unroll
            for (int e = 0; e < 2; e++) {
                int c = wn * 32 + fn * 8 + 2 * q + e;
                red_s[c][wm] = psum[fn][e];
                red_m[c][wm] = pmax[fn][e];
            }
    }
    __syncthreads();
    if (t < 128) {
        const int bb = m0 >> 9;
        float s = red_s[t][0] + red_s[t][1];
        float mx = fmaxf(red_m[t][0], red_m[t][1]);
        atomicAdd(&out[bb * 3072 + sumoff + n0 + t], s);
        atomicMax((int*)&out[bb * 3072 + maxoff + n0 + t], __float_as_int(mx));
    }
}

// zero out + stats accumulators (rm/cm encoded maxes, rs/cs sums)
__global__ void k_zero(float* __restrict__ out, float* __restrict__ stats)
{
    int i = blockIdx.x * blockDim.x + threadIdx.x;
    if (i < BB * 4 * HH) out[i] = 0.0f;
    if (i < 4 * M_ROWS) stats[i] = 0.0f;
}

extern "C" void kernel_launch(void* const* d_in, const int* in_sizes, int n_in,
                              void* d_out, int out_size)
{
    const float* a_embeds = (const float*)d_in[0];
    const float* b_embeds = (const float*)d_in[1];
    const int*   a_mask   = (const int*)d_in[2];
    const int*   b_mask   = (const int*)d_in[3];
    const float* Wp = (const float*)d_in[4];
    const float* bp = (const float*)d_in[5];
    const float* Wf = (const float*)d_in[6];
    const float* bf = (const float*)d_in[7];
    const float* Wg = (const float*)d_in[8];
    const float* bg = (const float*)d_in[9];
    float* out = (float*)d_out;

    float* base = nullptr;
    cudaGetSymbolAddress((void**)&base, g_scratch);
    float* att = base;
    float* rm  = att + ALL;          // encoded uint maxes
    float* cm  = rm + M_ROWS;
    float* rs  = cm + M_ROWS;
    float* cs  = rs + M_ROWS;
    __half* ah    = (__half*)(cs + M_ROWS);
    __half* bh    = ah + PLH;
    __half* ap    = bh + PLH;
    __half* bp_   = ap + PLH;
    __half* Fa    = bp_ + PLH;
    __half* Fb    = Fa + PLH;
    __half* beta  = Fb + PLH;
    __half* alpha = beta + PLH;
    __half* S1    = alpha + PLH;
    __half* S2t   = S1 + ALL;
    __half* hWp   = S2t + ALL;
    __half* hWf   = hWp + DD * HH;
    __half* hWg   = hWf + HH * HH;

    cudaFuncSetAttribute(k_proj, cudaFuncAttributeMaxDynamicSharedMemorySize, KN_SMEM);
    cudaFuncSetAttribute(k_att,  cudaFuncAttributeMaxDynamicSharedMemorySize, NT_SMEM);
    cudaFuncSetAttribute(k_ctx,  cudaFuncAttributeMaxDynamicSharedMemorySize, KN_SMEM);
    cudaFuncSetAttribute(k_cmp,  cudaFuncAttributeMaxDynamicSharedMemorySize, KN_SMEM);

    k_zero<<<(BB * 4 * HH + 1023) / 1024, 1024>>>(out, rm);

    // fp32 -> fp16 conversions
    k_cvth2<<<dim3((int)((PLH / 4 + 255) / 256), 1, 2), 256>>>(a_embeds, b_embeds, ah, bh, (int)PLH);
    k_cvtw<<<dim3((2 * HH * HH / 4 + 255) / 256, 1, 3), 256>>>(Wp, Wf, Wg, hWp, hWf, hWg);

    // shared projection FFN (paired a/b)
    k_proj<<<dim3(6, 256, 2), 256, KN_SMEM>>>(ah, bh, hWp, bp, nullptr, nullptr, ap, bp_, DD);

    // attend features (paired, relu + mask)
    k_proj<<<dim3(6, 256, 2), 256, KN_SMEM>>>(ap, bp_, hWf, bf, a_mask, b_mask, Fa, Fb, HH);

    // attention scores + fused row/col max
    k_att<<<dim3(4, 4, 64), 256, NT_SMEM>>>(Fa, Fb, att, (uint32_t*)rm, (uint32_t*)cm);

    // map: unnormalized softmax numerators + sum accumulation
    k_map<<<dim3(16, 16, 64), dim3(32, 8)>>>(att, a_mask, b_mask,
                                             (const uint32_t*)rm, (const uint32_t*)cm,
                                             rs, cs, S1, S2t);

    // contexts (paired; deferred normalization in epilogue)
    k_ctx<<<dim3(6, 4, 128), 256, KN_SMEM>>>(S1, S2t, bp_, ap, rs, cs, beta, alpha);

    // compare + aggregate (paired)
    k_cmp<<<dim3(6, 256, 2), 256, KN_SMEM>>>(ap, bp_, beta, alpha, hWg, bg, a_mask, b_mask, out);
}